// round 4
// baseline (speedup 1.0000x reference)
#include <cuda_runtime.h>

// Problem: CtcBoundaryLossV3 — fused single-launch, two-level completion.
// Inputs (metadata order):
//   d_in[0] alpha          float32 [B, T]
//   d_in[1] ctc_log_probs  float32 [B, T, V]
//   d_in[2] mask           float32 [B, T]
//   d_in[3] text_length    int32   [B]
// Output: float32 scalar.

#define SPLIT 8
#define MAXB  32
#define NBLK  128                     // threads per block

#define LOG_THR 1.0986122886681098f   // log(3.0)

__device__ float        g_psum[MAXB * SPLIT];
__device__ int          g_pcnt[MAXB * SPLIT];
__device__ float        g_rs[MAXB];
__device__ int          g_ns[MAXB];
__device__ unsigned int g_bcnt[MAXB * 32];   // per-batch counters, 128B apart
__device__ unsigned int g_ticket = 0;

__global__ void __launch_bounds__(NBLK)
ctc_fused_kernel(const float* __restrict__ alpha,
                 const float* __restrict__ ctc,
                 const float* __restrict__ mask,
                 const int*   __restrict__ tlen,
                 float* __restrict__ out,
                 int B, int T, int V, int chunkLen) {
    const int bid   = blockIdx.x;           // 0 .. B*SPLIT-1
    const int b     = bid / SPLIT;
    const int chunk = bid % SPLIT;
    const int t0    = chunk * chunkLen;
    const int tid   = threadIdx.x;

    float lsum = 0.0f;
    int   lcnt = 0;
    const size_t rowBase = (size_t)b * (size_t)T;

    const bool vecOK = ((chunkLen & 3) == 0) && ((t0 & 3) == 0) &&
                       (t0 + chunkLen <= T);

    if (vecOK) {
        // nvec float4 groups per array; half the block does alpha, half mask+blank
        const int nvec = chunkLen >> 2;
        const int half = NBLK >> 1;
        if (tid < half) {
            const float4* a4 = (const float4*)(alpha + rowBase + t0);
            for (int v = tid; v < nvec; v += half) {
                float4 a = a4[v];
                lsum += (a.x + a.y) + (a.z + a.w);
            }
        } else {
            const float4* m4 = (const float4*)(mask + rowBase + t0);
            const int j0 = tid - half;
            for (int v = j0; v < nvec; v += half) {
                float4 m = m4[v];
                const size_t base = (rowBase + (size_t)(t0 + v * 4)) * (size_t)V;
                float b0 = ctc[base];
                float b1 = ctc[base + (size_t)V];
                float b2 = ctc[base + 2 * (size_t)V];
                float b3 = ctc[base + 3 * (size_t)V];
                lcnt += (((1.0f - b0) > LOG_THR) && (m.x != 0.0f)) ? 1 : 0;
                lcnt += (((1.0f - b1) > LOG_THR) && (m.y != 0.0f)) ? 1 : 0;
                lcnt += (((1.0f - b2) > LOG_THR) && (m.z != 0.0f)) ? 1 : 0;
                lcnt += (((1.0f - b3) > LOG_THR) && (m.w != 0.0f)) ? 1 : 0;
            }
        }
    } else {
        const int tEnd = min(t0 + chunkLen, T);
        for (int t = t0 + tid; t < tEnd; t += NBLK) {
            const size_t idx = rowBase + (size_t)t;
            float a  = alpha[idx];
            float mk = mask[idx];
            float bl = ctc[idx * (size_t)V];
            lsum += a;
            lcnt += (((1.0f - bl) > LOG_THR) && (mk != 0.0f)) ? 1 : 0;
        }
    }

    // ---- block reduce (4 warps) ----
    #pragma unroll
    for (int off = 16; off > 0; off >>= 1) {
        lsum += __shfl_down_sync(0xFFFFFFFFu, lsum, off);
        lcnt += __shfl_down_sync(0xFFFFFFFFu, lcnt, off);
    }

    __shared__ float s_sum[4];
    __shared__ int   s_cnt[4];
    __shared__ int   s_amLast;
    const int wid = tid >> 5;
    const int lid = tid & 31;
    if (lid == 0) { s_sum[wid] = lsum; s_cnt[wid] = lcnt; }
    if (tid == 0) s_amLast = 0;
    __syncthreads();

    if (tid == 0) {
        float tsum = (s_sum[0] + s_sum[1]) + (s_sum[2] + s_sum[3]);
        int   tcnt = (s_cnt[0] + s_cnt[1]) + (s_cnt[2] + s_cnt[3]);
        g_psum[b * SPLIT + chunk] = tsum;
        g_pcnt[b * SPLIT + chunk] = tcnt;
        __threadfence();
        unsigned int bprev = atomicAdd(&g_bcnt[b * 32], 1u);
        if (bprev == (unsigned)(SPLIT - 1)) {
            // batch-last: combine this batch's partials
            float rs = 0.0f;
            int   ns = 0;
            #pragma unroll
            for (int c = 0; c < SPLIT; c++) {
                rs += g_psum[b * SPLIT + c];
                ns += g_pcnt[b * SPLIT + c];
            }
            g_rs[b] = rs;
            g_ns[b] = ns;
            __threadfence();
            unsigned int prev = atomicAdd(&g_ticket, 1u);
            if (prev == (unsigned)(B - 1)) {
                __threadfence();
                s_amLast = 1;
            }
        }
    }
    __syncthreads();

    // ---- global-last block finalizes with one warp ----
    if (!s_amLast || tid >= 32) return;

    const int lane = tid;

    float rs = 0.0f;
    int   ns = 0;
    int   tl = 1;
    if (lane < B) {
        rs = g_rs[lane];
        ns = g_ns[lane];
        tl = tlen[lane];
    }

    int len_i = (lane < B) ? ((ns >= 1) ? ns : 1) : 0;
    int tmx   = (lane < B) ? tl : 0;
    #pragma unroll
    for (int off = 16; off > 0; off >>= 1) {
        len_i = max(len_i, __shfl_xor_sync(0xFFFFFFFFu, len_i, off));
        tmx   = max(tmx,   __shfl_xor_sync(0xFFFFFFFFu, tmx,   off));
    }
    const int L = min(len_i, tmx);

    float ps = 0.0f;
    if (lane < B) {
        int m = min(tl, L);                 // m >= 1
        if (ns >= 1) {
            int k = min(ns, m);
            ps = (float)k * fabsf(rs - 1.0f) + (float)(m - k);
        } else {
            ps = (float)(m - 1);
        }
    }
    #pragma unroll
    for (int off = 16; off > 0; off >>= 1)
        ps += __shfl_xor_sync(0xFFFFFFFFu, ps, off);

    // reset counters for next graph replay
    if (lane < MAXB) g_bcnt[lane * 32] = 0;
    if (lane == 0) {
        out[0] = ps / (float)B;
        g_ticket = 0;
    }
}

extern "C" void kernel_launch(void* const* d_in, const int* in_sizes, int n_in,
                              void* d_out, int out_size) {
    const float* alpha = (const float*)d_in[0];
    const float* ctc   = (const float*)d_in[1];
    const float* mask  = (const float*)d_in[2];
    const int*   tlen  = (const int*)d_in[3];
    float*       out   = (float*)d_out;

    const int B  = in_sizes[3];
    const int BT = in_sizes[0];
    const int T  = BT / B;
    const int V  = in_sizes[1] / BT;
    const int chunkLen = (T + SPLIT - 1) / SPLIT;

    ctc_fused_kernel<<<B * SPLIT, NBLK>>>(alpha, ctc, mask, tlen, out,
                                          B, T, V, chunkLen);
}

// round 5
// speedup vs baseline: 1.0449x; 1.0449x over previous
#include <cuda_runtime.h>

// Problem: CtcBoundaryLossV3 — fused single-launch, atomic-accumulate version.
// Inputs (metadata order):
//   d_in[0] alpha          float32 [B, T]
//   d_in[1] ctc_log_probs  float32 [B, T, V]
//   d_in[2] mask           float32 [B, T]
//   d_in[3] text_length    int32   [B]
// Output: float32 scalar.

#define SPLIT 16
#define MAXB  32
#define NBLK  128                     // threads per block == frames per chunk

#define LOG_THR 1.0986122886681098f   // log(3.0)

__device__ float        g_rs[MAXB];     // zeroed by finalize for next replay
__device__ int          g_ns[MAXB];
__device__ unsigned int g_ticket = 0;

__global__ void __launch_bounds__(NBLK)
ctc_fused_kernel(const float* __restrict__ alpha,
                 const float* __restrict__ ctc,
                 const float* __restrict__ mask,
                 const int*   __restrict__ tlen,
                 float* __restrict__ out,
                 int B, int T, int V, int chunkLen) {
    const int bid   = blockIdx.x;           // 0 .. B*SPLIT-1
    const int b     = bid / SPLIT;
    const int chunk = bid % SPLIT;
    const int tid   = threadIdx.x;
    const int t     = chunk * chunkLen + tid;

    // ---- Phase 1: one frame per thread ----
    float lsum = 0.0f;
    int   lcnt = 0;
    if (t < T) {
        const size_t idx = (size_t)b * (size_t)T + (size_t)t;
        float a  = alpha[idx];
        float mk = mask[idx];
        float bl = ctc[idx * (size_t)V];    // blank column (index 0)
        lsum = a;
        lcnt = (((1.0f - bl) > LOG_THR) && (mk != 0.0f)) ? 1 : 0;
    }

    // ---- block reduce (4 warps) ----
    #pragma unroll
    for (int off = 16; off > 0; off >>= 1) {
        lsum += __shfl_down_sync(0xFFFFFFFFu, lsum, off);
        lcnt += __shfl_down_sync(0xFFFFFFFFu, lcnt, off);
    }

    __shared__ float s_sum[4];
    __shared__ int   s_cnt[4];
    __shared__ int   s_amLast;
    const int wid = tid >> 5;
    const int lid = tid & 31;
    if (lid == 0) { s_sum[wid] = lsum; s_cnt[wid] = lcnt; }
    if (tid == 0) s_amLast = 0;
    __syncthreads();

    if (tid == 0) {
        float tsum = (s_sum[0] + s_sum[1]) + (s_sum[2] + s_sum[3]);
        int   tcnt = (s_cnt[0] + s_cnt[1]) + (s_cnt[2] + s_cnt[3]);
        atomicAdd(&g_rs[b], tsum);
        atomicAdd(&g_ns[b], tcnt);
        __threadfence();
        unsigned int prev = atomicAdd(&g_ticket, 1u);
        s_amLast = (prev == gridDim.x - 1u);
    }
    __syncthreads();

    // ---- Phase 2: global-last block finalizes with one warp ----
    if (!s_amLast || tid >= 32) return;

    const int lane = tid;

    float rs = 0.0f;
    int   ns = 0;
    int   tl = 1;
    if (lane < B) {
        rs = g_rs[lane];
        ns = g_ns[lane];
        tl = tlen[lane];
    }

    // L = min( max_b len_i , max_b text_length )
    int len_i = (lane < B) ? ((ns >= 1) ? ns : 1) : 0;
    int tmx   = (lane < B) ? tl : 0;
    #pragma unroll
    for (int off = 16; off > 0; off >>= 1) {
        len_i = max(len_i, __shfl_xor_sync(0xFFFFFFFFu, len_i, off));
        tmx   = max(tmx,   __shfl_xor_sync(0xFFFFFFFFu, tmx,   off));
    }
    const int L = min(len_i, tmx);

    float ps = 0.0f;
    if (lane < B) {
        int m = min(tl, L);                 // m >= 1 (tl >= 1, L >= 1)
        if (ns >= 1) {
            int k = min(ns, m);
            ps = (float)k * fabsf(rs - 1.0f) + (float)(m - k);
        } else {
            ps = (float)(m - 1);
        }
    }
    #pragma unroll
    for (int off = 16; off > 0; off >>= 1)
        ps += __shfl_xor_sync(0xFFFFFFFFu, ps, off);

    // write result + reset state for next graph replay
    if (lane < MAXB) { g_rs[lane] = 0.0f; g_ns[lane] = 0; }
    if (lane == 0) {
        out[0] = ps / (float)B;
        g_ticket = 0;
    }
}

extern "C" void kernel_launch(void* const* d_in, const int* in_sizes, int n_in,
                              void* d_out, int out_size) {
    const float* alpha = (const float*)d_in[0];
    const float* ctc   = (const float*)d_in[1];
    const float* mask  = (const float*)d_in[2];
    const int*   tlen  = (const int*)d_in[3];
    float*       out   = (float*)d_out;

    const int B  = in_sizes[3];
    const int BT = in_sizes[0];
    const int T  = BT / B;
    const int V  = in_sizes[1] / BT;
    const int chunkLen = (T + SPLIT - 1) / SPLIT;   // frames per block

    ctc_fused_kernel<<<B * SPLIT, NBLK>>>(alpha, ctc, mask, tlen, out,
                                          B, T, V, chunkLen);
}